// round 13
// baseline (speedup 1.0000x reference)
#include <cuda_runtime.h>
#include <cstdint>

// Problem constants
#define Hdim   64
#define Wdim   64
#define HW     4096          // 64*64
#define CIN    256
#define COUT   256
#define BATCH  4
#define KK     9             // 3x3 taps
#define PDIM   (CIN * KK)    // 2304, GEMM K dimension
#define NSPLIT 8             // channel splits for offsets conv

// Scratch (static device globals; no allocation anywhere)
__device__ float g_offp[NSPLIT][BATCH * 18 * HW];        // partial offsets (per channel split)
__device__ float g_val[(size_t)BATCH * PDIM * HW];       // bilinear-sampled matrix (tf32-rounded)
__device__ float g_wdefP[COUT * PDIM];                   // tf32-rounded, k-permuted w_def

__device__ __forceinline__ float f2tf32(float f) {
    unsigned r;
    asm("cvt.rna.tf32.f32 %0, %1;" : "=r"(r) : "f"(f));
    return __uint_as_float(r);
}

__device__ __forceinline__ uint32_t smem_u32(const void* p) {
    uint32_t a;
    asm("{ .reg .u64 t; cvta.to.shared.u64 t, %1; cvt.u32.u64 %0, t; }" : "=r"(a) : "l"(p));
    return a;
}
__device__ __forceinline__ void cp16(uint32_t dst, const void* src) {
    asm volatile("cp.async.cg.shared.global [%0], [%1], 16;" :: "r"(dst), "l"(src));
}
#define CP_COMMIT() asm volatile("cp.async.commit_group;" ::: "memory")
#define CP_WAIT(n)  asm volatile("cp.async.wait_group %0;" :: "n"(n) : "memory")

// ---------------------------------------------------------------------------
// Kernel 0: pre-round w_def to tf32 AND pre-permute k within each 16-group:
// stored float4 group p covers k = {t, t+4, t+8, t+12}. phys p -> orig k:
// k = (p>>2) + 4*(p&1) + 8*((p>>1)&1).
// ---------------------------------------------------------------------------
__global__ __launch_bounds__(256) void round_a_kernel(const float* __restrict__ w)
{
    int i = blockIdx.x * blockDim.x + threadIdx.x;
    if (i >= COUT * PDIM) return;
    int m   = i / PDIM;
    int pos = i % PDIM;
    int kt  = pos & ~15;
    int p   = pos & 15;
    int k   = (p >> 2) + 4 * (p & 1) + 8 * ((p >> 1) & 1);
    g_wdefP[i] = f2tf32(w[(size_t)m * PDIM + kt + k]);
}

// ---------------------------------------------------------------------------
// Kernel 1: partial offsets conv (unchanged; passing since round 6)
// ---------------------------------------------------------------------------
__global__ __launch_bounds__(128) void offsets_part_kernel(
    const float* __restrict__ x, const float* __restrict__ w_off)
{
    __shared__ float ws[8][9][20];
    __shared__ float xs[8][4][68];

    const int blk   = blockIdx.x;
    const int split = blockIdx.y;
    const int b     = blk >> 5;
    const int row2  = (blk & 31) * 2;
    const int hr    = threadIdx.x >> 6;
    const int wo    = threadIdx.x & 63;

    const int cxm1 = (wo == 0)  ? 64 : wo - 1;
    const int cx0  = wo;
    const int cxp1 = (wo == 63) ? 65 : wo + 1;

    if (threadIdx.x < 64) {
        int c = threadIdx.x >> 3;
        int r = (threadIdx.x >> 1) & 3;
        xs[c][r][64 + (threadIdx.x & 1)] = 0.f;
    }

    float acc[18];
#pragma unroll
    for (int o = 0; o < 18; o++) acc[o] = 0.f;

    const float* xb = x + (size_t)b * CIN * HW;
    const int cbase = split * (CIN / NSPLIT);

    const int lc  = threadIdx.x >> 4;
    const int lr  = (threadIdx.x >> 2) & 3;
    const int lsg = (threadIdx.x & 3) * 16;
    const int ly  = row2 - 1 + lr;
    const bool lyv = (ly >= 0) && (ly < Hdim);

    for (int c0 = cbase; c0 < cbase + CIN / NSPLIT; c0 += 8) {
        __syncthreads();
        for (int i = threadIdx.x; i < 18 * 8 * 9; i += 128) {
            int oc = i / 72; int rem = i % 72; int c = rem / 9; int tap = rem % 9;
            ws[c][tap][oc] = w_off[(size_t)oc * CIN * 9 + (size_t)(c0 + c) * 9 + tap];
        }
        {
            float4 v[4];
            if (lyv) {
                const float* xr = xb + (size_t)(c0 + lc) * HW + ly * Wdim + lsg;
#pragma unroll
                for (int j = 0; j < 4; j++) v[j] = *(const float4*)(xr + j * 4);
            } else {
#pragma unroll
                for (int j = 0; j < 4; j++) v[j] = make_float4(0.f, 0.f, 0.f, 0.f);
            }
#pragma unroll
            for (int j = 0; j < 4; j++)
                *(float4*)&xs[lc][lr][lsg + j * 4] = v[j];
        }
        __syncthreads();

#pragma unroll
        for (int c = 0; c < 8; c++) {
            float xv[9];
#pragma unroll
            for (int ky = 0; ky < 3; ky++) {
                const float* row = xs[c][hr + ky];
                xv[ky * 3 + 0] = row[cxm1];
                xv[ky * 3 + 1] = row[cx0];
                xv[ky * 3 + 2] = row[cxp1];
            }
#pragma unroll
            for (int tap = 0; tap < 9; tap++) {
                float xt = xv[tap];
#pragma unroll
                for (int o = 0; o < 18; o++)
                    acc[o] += xt * ws[c][tap][o];
            }
        }
    }

    const int hw = (row2 + hr) * Wdim + wo;
#pragma unroll
    for (int o = 0; o < 18; o++)
        g_offp[split][((size_t)b * 18 + o) * HW + hw] = acc[o];
}

// ---------------------------------------------------------------------------
// Kernel 2: bilinear gather -> g_val[b][c*9+k][hw], tf32-rounded (unchanged)
// ---------------------------------------------------------------------------
__global__ __launch_bounds__(256) void gather_kernel(const float* __restrict__ x)
{
    int idx = blockIdx.x * blockDim.x + threadIdx.x;
    if (idx >= BATCH * KK * HW) return;
    int hw = idx & 4095;
    int k  = (idx >> 12) % KK;
    int b  = idx / (KK * HW);
    int ho = hw >> 6, wo = hw & 63;
    int ky = k / 3,  kx = k % 3;

    const size_t oy = ((size_t)b * 18 + 2 * k + 0) * HW + hw;
    const size_t ox = ((size_t)b * 18 + 2 * k + 1) * HW + hw;
    float dy = 0.f, dx = 0.f;
#pragma unroll
    for (int s = 0; s < NSPLIT; s++) {
        dy += g_offp[s][oy];
        dx += g_offp[s][ox];
    }

    float py = (float)(ho - 1 + ky) + dy;
    float px = (float)(wo - 1 + kx) + dx;
    float y0f = floorf(py), x0f = floorf(px);
    int   y0 = (int)y0f,    x0 = (int)x0f;
    float wy1 = py - y0f, wx1 = px - x0f;
    float wy0 = 1.f - wy1, wx0 = 1.f - wx1;
    int y1 = y0 + 1, x1 = x0 + 1;

    bool vy0 = (y0 >= 0) & (y0 < Hdim);
    bool vy1 = (y1 >= 0) & (y1 < Hdim);
    bool vx0 = (x0 >= 0) & (x0 < Wdim);
    bool vx1 = (x1 >= 0) & (x1 < Wdim);

    float w00 = (vy0 && vx0) ? wy0 * wx0 : 0.f;
    float w01 = (vy0 && vx1) ? wy0 * wx1 : 0.f;
    float w10 = (vy1 && vx0) ? wy1 * wx0 : 0.f;
    float w11 = (vy1 && vx1) ? wy1 * wx1 : 0.f;

    int y0c = min(max(y0, 0), Hdim - 1), y1c = min(max(y1, 0), Hdim - 1);
    int x0c = min(max(x0, 0), Wdim - 1), x1c = min(max(x1, 0), Wdim - 1);
    int i00 = y0c * Wdim + x0c, i01 = y0c * Wdim + x1c;
    int i10 = y1c * Wdim + x0c, i11 = y1c * Wdim + x1c;

    const float* xb = x + (size_t)b * CIN * HW;
    float* vout = g_val + ((size_t)b * PDIM + k) * HW + hw;

    for (int c = 0; c < CIN; c++) {
        const float* xc = xb + c * HW;
        float v = w00 * __ldg(xc + i00) + w01 * __ldg(xc + i01)
                + w10 * __ldg(xc + i10) + w11 * __ldg(xc + i11);
        vout[(size_t)c * KK * HW] = f2tf32(v);
    }
}

// ---------------------------------------------------------------------------
// Kernel 3: TF32 mma.sync GEMM, 3-stage cp.async pipeline, BK=32.
// Block 128x128, 256 thr (8 warps 2x4), warp 64x32; 72 mainloop iters.
// A stage: GROUP-MAJOR [2 k16-groups][128 rows][16 floats] — preserves the
//   proven conflict-free SA=16 fragment math per group (flat [128][32]
//   would alias banks: 32-float row stride == 0 mod 8 banks16).
// B stage: [32 k][136 floats]; group offset 16*136 == 0 mod 32 banks32 ->
//   LDS.32 fragments stay conflict-free.
// STAGES=3, wait_group 1. Dynamic smem: 3*(16384+17408) = 101376 B,
// 2 CTAs/SM = 198KB < 228KB.
// ---------------------------------------------------------------------------
#define BM 128
#define BN 128
#define BK 32
#define SA 16    // floats per row within a k16 group
#define SB 136   // Bs row stride (floats)
#define STAGES 3
#define A_GRP (BM * SA)            // 2048 floats per k16 group
#define A_STG (2 * A_GRP)          // 4096 floats per A stage
#define B_STG (BK * SB)            // 4352 floats per B stage
#define B_BASE (STAGES * A_STG)    // float offset of B region
#define SMEM_GEMM_BYTES ((STAGES * (A_STG + B_STG)) * 4)   // 101376

__device__ __forceinline__ void mma_tf32(float4& d, float a0, float a1, float a2, float a3,
                                         float b0, float b1) {
    asm volatile(
        "mma.sync.aligned.m16n8k8.row.col.f32.tf32.tf32.f32 "
        "{%0,%1,%2,%3}, {%4,%5,%6,%7}, {%8,%9}, {%0,%1,%2,%3};"
        : "+f"(d.x), "+f"(d.y), "+f"(d.z), "+f"(d.w)
        : "r"(__float_as_uint(a0)), "r"(__float_as_uint(a1)),
          "r"(__float_as_uint(a2)), "r"(__float_as_uint(a3)),
          "r"(__float_as_uint(b0)), "r"(__float_as_uint(b1)));
}

__global__ __launch_bounds__(256, 2) void mma_gemm_kernel(float* __restrict__ C)
{
    extern __shared__ float sm[];

    const int b  = blockIdx.z;
    const float* Bp = g_val + (size_t)b * PDIM * HW;
    float*       Cp = C     + (size_t)b * COUT * HW;
    const int m0 = blockIdx.y * BM;
    const int n0 = blockIdx.x * BN;

    const int tid  = threadIdx.x;
    const int warp = tid >> 5;
    const int lane = tid & 31;
    const int g = lane >> 2;            // 0..7
    const int t = lane & 3;             // 0..3
    const int wm = (warp >> 2) * 64;    // warp M offset
    const int wn = (warp & 3) * 32;     // warp N offset

    float4 acc[4][4];
#pragma unroll
    for (int i = 0; i < 4; i++)
#pragma unroll
        for (int j = 0; j < 4; j++) acc[i][j] = make_float4(0.f, 0.f, 0.f, 0.f);

    // staging maps (per stage, per thread: 4 A cp16 + 4 B cp16)
    // A: row = tid>>1, group = tid&1 (16 floats of that group's row)
    const int arow = tid >> 1, agrp = tid & 1;
    const float* aP = g_wdefP + (size_t)(m0 + arow) * PDIM + agrp * 16;
    // B: k-row = tid>>3, n segment = (tid&7)*16
    const int bk = tid >> 3, bj = tid & 7;
    const float* bP = Bp + (size_t)bk * HW + n0 + bj * 16;

    const uint32_t smb = smem_u32(sm);
    const uint32_t aoff = (uint32_t)(agrp * A_GRP + arow * SA) * 4;
    const uint32_t boff = (uint32_t)(B_BASE + bk * SB + bj * 16) * 4;

    const int nk = PDIM / BK;   // 72

    // prologue: issue STAGES-1 tile copies
#pragma unroll
    for (int p = 0; p < STAGES - 1; p++) {
        const size_t kt = (size_t)p * BK;
        const uint32_t ad = smb + aoff + p * (A_STG * 4);
        const uint32_t bd = smb + boff + p * (B_STG * 4);
#pragma unroll
        for (int j = 0; j < 4; j++) cp16(ad + j * 16, aP + kt + j * 4);
#pragma unroll
        for (int j = 0; j < 4; j++) cp16(bd + j * 16, bP + kt * HW + j * 4);
        CP_COMMIT();
    }

    int s = 0;
    for (int it = 0; it < nk; it++) {
        const float* Asf = sm + s * A_STG;
        const float* Bsf = sm + B_BASE + s * B_STG;

        CP_WAIT(STAGES - 2);
        __syncthreads();

        // issue copy for tile it+STAGES-1 into the stage just freed
        if (it + STAGES - 1 < nk) {
            int d = s + STAGES - 1; if (d >= STAGES) d -= STAGES;
            const size_t kt = (size_t)(it + STAGES - 1) * BK;
            const uint32_t ad = smb + aoff + d * (A_STG * 4);
            const uint32_t bd = smb + boff + d * (B_STG * 4);
#pragma unroll
            for (int j = 0; j < 4; j++) cp16(ad + j * 16, aP + kt + j * 4);
#pragma unroll
            for (int j = 0; j < 4; j++) cp16(bd + j * 16, bP + kt * HW + j * 4);
            CP_COMMIT();
        }

        // two k16 groups per stage
#pragma unroll
        for (int grp = 0; grp < 2; grp++) {
            const float* Ag = Asf + grp * A_GRP;
            const float* Bg = Bsf + grp * 16 * SB;

            // B fragments: 4 LDS.32 each, conflict-free
            float4 BB[4];
#pragma unroll
            for (int nt = 0; nt < 4; nt++) {
                const int n = wn + nt * 8 + g;
                BB[nt].x = Bg[(t     ) * SB + n];
                BB[nt].y = Bg[(t + 4 ) * SB + n];
                BB[nt].z = Bg[(t + 8 ) * SB + n];
                BB[nt].w = Bg[(t + 12) * SB + n];
            }

#pragma unroll
            for (int half = 0; half < 2; half++) {
                float4 AL[2], AH[2];
#pragma unroll
                for (int m = 0; m < 2; m++) {
                    const int mr = wm + (half * 2 + m) * 16 + g;
                    AL[m] = *(const float4*)&Ag[mr * SA + 4 * t];
                    AH[m] = *(const float4*)&Ag[(mr + 8) * SA + 4 * t];
                }
#pragma unroll
                for (int m = 0; m < 2; m++) {
                    const int mt = half * 2 + m;
#pragma unroll
                    for (int nt = 0; nt < 4; nt++) {
                        mma_tf32(acc[mt][nt], AL[m].x, AH[m].x, AL[m].y, AH[m].y,
                                 BB[nt].x, BB[nt].y);
                        mma_tf32(acc[mt][nt], AL[m].z, AH[m].z, AL[m].w, AH[m].w,
                                 BB[nt].z, BB[nt].w);
                    }
                }
            }
        }

        if (++s == STAGES) s = 0;
    }

    __syncthreads();

    // epilogue: D fragments -> gmem
#pragma unroll
    for (int mt = 0; mt < 4; mt++) {
#pragma unroll
        for (int nt = 0; nt < 4; nt++) {
            const int row = m0 + wm + mt * 16 + g;
            const int col = n0 + wn + nt * 8 + 2 * t;
            float4 d = acc[mt][nt];
            *(float2*)(Cp + (size_t)row * HW + col)       = make_float2(d.x, d.y);
            *(float2*)(Cp + (size_t)(row + 8) * HW + col) = make_float2(d.z, d.w);
        }
    }
}

// ---------------------------------------------------------------------------
extern "C" void kernel_launch(void* const* d_in, const int* in_sizes, int n_in,
                              void* d_out, int out_size)
{
    const float* x     = (const float*)d_in[0];   // (4,256,64,64)
    const float* w_def = (const float*)d_in[1];   // (256,256,3,3)
    const float* w_off = (const float*)d_in[2];   // (18,256,3,3)
    float* out = (float*)d_out;                   // (4,256,64,64)

    cudaFuncSetAttribute(mma_gemm_kernel,
                         cudaFuncAttributeMaxDynamicSharedMemorySize, SMEM_GEMM_BYTES);

    round_a_kernel<<<(COUT * PDIM + 255) / 256, 256>>>(w_def);
    offsets_part_kernel<<<dim3(BATCH * 32, NSPLIT), 128>>>(x, w_off);
    gather_kernel<<<(BATCH * KK * HW + 255) / 256, 256>>>(x);
    mma_gemm_kernel<<<dim3(HW / BN, COUT / BM, BATCH), 256, SMEM_GEMM_BYTES>>>(out);
}

// round 14
// speedup vs baseline: 1.2794x; 1.2794x over previous
#include <cuda_runtime.h>
#include <cstdint>

// Problem constants
#define Hdim   64
#define Wdim   64
#define HW     4096          // 64*64
#define CIN    256
#define COUT   256
#define BATCH  4
#define KK     9             // 3x3 taps
#define PDIM   (CIN * KK)    // 2304, GEMM K dimension
#define NSPLIT 8             // channel splits for offsets conv

// Scratch (static device globals; no allocation anywhere)
__device__ float g_offp[NSPLIT][BATCH * 18 * HW];        // partial offsets (per channel split)
__device__ float g_val[(size_t)BATCH * PDIM * HW];       // bilinear-sampled matrix (tf32-rounded)
__device__ float g_wdefP[COUT * PDIM];                   // tf32-rounded, k-permuted w_def

__device__ __forceinline__ float f2tf32(float f) {
    unsigned r;
    asm("cvt.rna.tf32.f32 %0, %1;" : "=r"(r) : "f"(f));
    return __uint_as_float(r);
}

__device__ __forceinline__ uint32_t smem_u32(const void* p) {
    uint32_t a;
    asm("{ .reg .u64 t; cvta.to.shared.u64 t, %1; cvt.u32.u64 %0, t; }" : "=r"(a) : "l"(p));
    return a;
}
__device__ __forceinline__ void cp16(uint32_t dst, const void* src) {
    asm volatile("cp.async.cg.shared.global [%0], [%1], 16;" :: "r"(dst), "l"(src));
}
#define CP_COMMIT() asm volatile("cp.async.commit_group;" ::: "memory")
#define CP_WAIT(n)  asm volatile("cp.async.wait_group %0;" :: "n"(n) : "memory")

// ---------------------------------------------------------------------------
// Kernel 0: pre-round w_def to tf32 AND pre-permute k within each 16-group:
// stored float4 group p covers k = {t, t+4, t+8, t+12}. phys p -> orig k:
// k = (p>>2) + 4*(p&1) + 8*((p>>1)&1).
// ---------------------------------------------------------------------------
__global__ __launch_bounds__(256) void round_a_kernel(const float* __restrict__ w)
{
    int i = blockIdx.x * blockDim.x + threadIdx.x;
    if (i >= COUT * PDIM) return;
    int m   = i / PDIM;
    int pos = i % PDIM;
    int kt  = pos & ~15;
    int p   = pos & 15;
    int k   = (p >> 2) + 4 * (p & 1) + 8 * ((p >> 1) & 1);
    g_wdefP[i] = f2tf32(w[(size_t)m * PDIM + kt + k]);
}

// ---------------------------------------------------------------------------
// Kernel 1: partial offsets conv (unchanged; passing since round 6)
// ---------------------------------------------------------------------------
__global__ __launch_bounds__(128) void offsets_part_kernel(
    const float* __restrict__ x, const float* __restrict__ w_off)
{
    __shared__ float ws[8][9][20];
    __shared__ float xs[8][4][68];

    const int blk   = blockIdx.x;
    const int split = blockIdx.y;
    const int b     = blk >> 5;
    const int row2  = (blk & 31) * 2;
    const int hr    = threadIdx.x >> 6;
    const int wo    = threadIdx.x & 63;

    const int cxm1 = (wo == 0)  ? 64 : wo - 1;
    const int cx0  = wo;
    const int cxp1 = (wo == 63) ? 65 : wo + 1;

    if (threadIdx.x < 64) {
        int c = threadIdx.x >> 3;
        int r = (threadIdx.x >> 1) & 3;
        xs[c][r][64 + (threadIdx.x & 1)] = 0.f;
    }

    float acc[18];
#pragma unroll
    for (int o = 0; o < 18; o++) acc[o] = 0.f;

    const float* xb = x + (size_t)b * CIN * HW;
    const int cbase = split * (CIN / NSPLIT);

    const int lc  = threadIdx.x >> 4;
    const int lr  = (threadIdx.x >> 2) & 3;
    const int lsg = (threadIdx.x & 3) * 16;
    const int ly  = row2 - 1 + lr;
    const bool lyv = (ly >= 0) && (ly < Hdim);

    for (int c0 = cbase; c0 < cbase + CIN / NSPLIT; c0 += 8) {
        __syncthreads();
        for (int i = threadIdx.x; i < 18 * 8 * 9; i += 128) {
            int oc = i / 72; int rem = i % 72; int c = rem / 9; int tap = rem % 9;
            ws[c][tap][oc] = w_off[(size_t)oc * CIN * 9 + (size_t)(c0 + c) * 9 + tap];
        }
        {
            float4 v[4];
            if (lyv) {
                const float* xr = xb + (size_t)(c0 + lc) * HW + ly * Wdim + lsg;
#pragma unroll
                for (int j = 0; j < 4; j++) v[j] = *(const float4*)(xr + j * 4);
            } else {
#pragma unroll
                for (int j = 0; j < 4; j++) v[j] = make_float4(0.f, 0.f, 0.f, 0.f);
            }
#pragma unroll
            for (int j = 0; j < 4; j++)
                *(float4*)&xs[lc][lr][lsg + j * 4] = v[j];
        }
        __syncthreads();

#pragma unroll
        for (int c = 0; c < 8; c++) {
            float xv[9];
#pragma unroll
            for (int ky = 0; ky < 3; ky++) {
                const float* row = xs[c][hr + ky];
                xv[ky * 3 + 0] = row[cxm1];
                xv[ky * 3 + 1] = row[cx0];
                xv[ky * 3 + 2] = row[cxp1];
            }
#pragma unroll
            for (int tap = 0; tap < 9; tap++) {
                float xt = xv[tap];
#pragma unroll
                for (int o = 0; o < 18; o++)
                    acc[o] += xt * ws[c][tap][o];
            }
        }
    }

    const int hw = (row2 + hr) * Wdim + wo;
#pragma unroll
    for (int o = 0; o < 18; o++)
        g_offp[split][((size_t)b * 18 + o) * HW + hw] = acc[o];
}

// ---------------------------------------------------------------------------
// Kernel 2: bilinear gather -> g_val[b][c*9+k][hw], tf32-rounded (unchanged)
// ---------------------------------------------------------------------------
__global__ __launch_bounds__(256) void gather_kernel(const float* __restrict__ x)
{
    int idx = blockIdx.x * blockDim.x + threadIdx.x;
    if (idx >= BATCH * KK * HW) return;
    int hw = idx & 4095;
    int k  = (idx >> 12) % KK;
    int b  = idx / (KK * HW);
    int ho = hw >> 6, wo = hw & 63;
    int ky = k / 3,  kx = k % 3;

    const size_t oy = ((size_t)b * 18 + 2 * k + 0) * HW + hw;
    const size_t ox = ((size_t)b * 18 + 2 * k + 1) * HW + hw;
    float dy = 0.f, dx = 0.f;
#pragma unroll
    for (int s = 0; s < NSPLIT; s++) {
        dy += g_offp[s][oy];
        dx += g_offp[s][ox];
    }

    float py = (float)(ho - 1 + ky) + dy;
    float px = (float)(wo - 1 + kx) + dx;
    float y0f = floorf(py), x0f = floorf(px);
    int   y0 = (int)y0f,    x0 = (int)x0f;
    float wy1 = py - y0f, wx1 = px - x0f;
    float wy0 = 1.f - wy1, wx0 = 1.f - wx1;
    int y1 = y0 + 1, x1 = x0 + 1;

    bool vy0 = (y0 >= 0) & (y0 < Hdim);
    bool vy1 = (y1 >= 0) & (y1 < Hdim);
    bool vx0 = (x0 >= 0) & (x0 < Wdim);
    bool vx1 = (x1 >= 0) & (x1 < Wdim);

    float w00 = (vy0 && vx0) ? wy0 * wx0 : 0.f;
    float w01 = (vy0 && vx1) ? wy0 * wx1 : 0.f;
    float w10 = (vy1 && vx0) ? wy1 * wx0 : 0.f;
    float w11 = (vy1 && vx1) ? wy1 * wx1 : 0.f;

    int y0c = min(max(y0, 0), Hdim - 1), y1c = min(max(y1, 0), Hdim - 1);
    int x0c = min(max(x0, 0), Wdim - 1), x1c = min(max(x1, 0), Wdim - 1);
    int i00 = y0c * Wdim + x0c, i01 = y0c * Wdim + x1c;
    int i10 = y1c * Wdim + x0c, i11 = y1c * Wdim + x1c;

    const float* xb = x + (size_t)b * CIN * HW;
    float* vout = g_val + ((size_t)b * PDIM + k) * HW + hw;

    for (int c = 0; c < CIN; c++) {
        const float* xc = xb + c * HW;
        float v = w00 * __ldg(xc + i00) + w01 * __ldg(xc + i01)
                + w10 * __ldg(xc + i10) + w11 * __ldg(xc + i11);
        vout[(size_t)c * KK * HW] = f2tf32(v);
    }
}

// ---------------------------------------------------------------------------
// Kernel 3: TF32 mma.sync GEMM, 4-stage cp.async pipeline (round-11 config,
// reverted from the failed BK=32 experiment), with the MMA loop reordered:
// k8 step OUTERMOST within each mt-half so the two MMAs updating the same
// accumulator are 8 independent MMAs apart (was back-to-back RAW).
// Accumulation order per element unchanged (k8=0 before k8=1) -> bit-identical.
// Block 128x128, BK=16, 256 thr (8 warps 2x4), warp 64x32.
// As[s][row][16] (SA=16): fragment LDS.128 conflict-free.
// Bs[s][k][136]: LDS.32 fragments conflict-free. STAGES=4, wait_group 2.
// Dynamic smem: 4*(8192 + 8704) = 67584 B.
// ---------------------------------------------------------------------------
#define BM 128
#define BN 128
#define BK 16
#define SA 16    // As row stride (floats) — conflict-free for 4t-based LDS.128
#define SB 136   // Bs row stride (floats)
#define STAGES 4
#define A_STG (BM * SA)            // 2048 floats per A stage
#define B_STG (BK * SB)            // 2176 floats per B stage
#define B_BASE (STAGES * A_STG)    // float offset of B region
#define SMEM_GEMM_BYTES ((STAGES * (A_STG + B_STG)) * 4)   // 67584

__device__ __forceinline__ void mma_tf32(float4& d, float a0, float a1, float a2, float a3,
                                         float b0, float b1) {
    asm volatile(
        "mma.sync.aligned.m16n8k8.row.col.f32.tf32.tf32.f32 "
        "{%0,%1,%2,%3}, {%4,%5,%6,%7}, {%8,%9}, {%0,%1,%2,%3};"
        : "+f"(d.x), "+f"(d.y), "+f"(d.z), "+f"(d.w)
        : "r"(__float_as_uint(a0)), "r"(__float_as_uint(a1)),
          "r"(__float_as_uint(a2)), "r"(__float_as_uint(a3)),
          "r"(__float_as_uint(b0)), "r"(__float_as_uint(b1)));
}

__global__ __launch_bounds__(256, 2) void mma_gemm_kernel(float* __restrict__ C)
{
    extern __shared__ float sm[];

    const int b  = blockIdx.z;
    const float* Bp = g_val + (size_t)b * PDIM * HW;
    float*       Cp = C     + (size_t)b * COUT * HW;
    const int m0 = blockIdx.y * BM;
    const int n0 = blockIdx.x * BN;

    const int tid  = threadIdx.x;
    const int warp = tid >> 5;
    const int lane = tid & 31;
    const int g = lane >> 2;            // 0..7
    const int t = lane & 3;             // 0..3
    const int wm = (warp >> 2) * 64;    // warp M offset
    const int wn = (warp & 3) * 32;     // warp N offset

    float4 acc[4][4];
#pragma unroll
    for (int i = 0; i < 4; i++)
#pragma unroll
        for (int j = 0; j < 4; j++) acc[i][j] = make_float4(0.f, 0.f, 0.f, 0.f);

    // staging maps
    const int arow = tid >> 1, ah = tid & 1;
    const float* aP = g_wdefP + (size_t)(m0 + arow) * PDIM + ah * 8;
    const int bk = tid >> 4, bj = tid & 15;
    const float* bP = Bp + (size_t)bk * HW + n0 + bj * 4;

    const uint32_t smb = smem_u32(sm);
    const uint32_t aoff = (uint32_t)(arow * SA + ah * 8) * 4;
    const uint32_t boff = (uint32_t)(B_BASE + bk * SB + bj * 4) * 4;

    const int nk = PDIM / BK;   // 144

    // prologue: issue STAGES-1 tile copies (one commit group each)
#pragma unroll
    for (int p = 0; p < STAGES - 1; p++) {
        const size_t kt = (size_t)p * BK;
        const uint32_t ad = smb + aoff + p * (A_STG * 4);
        const uint32_t bd = smb + boff + p * (B_STG * 4);
        cp16(ad,      aP + kt);
        cp16(ad + 16, aP + kt + 4);
        cp16(bd,       bP + kt * HW);
        cp16(bd + 256, bP + kt * HW + 64);
        CP_COMMIT();
    }

    for (int it = 0; it < nk; it++) {
        const int s = it & (STAGES - 1);
        const float* Asf = sm + s * A_STG;
        const float* Bsf = sm + B_BASE + s * B_STG;

        CP_WAIT(STAGES - 2);
        __syncthreads();

        // issue copy for tile it+STAGES-1 into stage (s-1)%STAGES
        if (it + STAGES - 1 < nk) {
            const int d = (s + STAGES - 1) & (STAGES - 1);
            const size_t kt = (size_t)(it + STAGES - 1) * BK;
            const uint32_t ad = smb + aoff + d * (A_STG * 4);
            const uint32_t bd = smb + boff + d * (B_STG * 4);
            cp16(ad,      aP + kt);
            cp16(ad + 16, aP + kt + 4);
            cp16(bd,       bP + kt * HW);
            cp16(bd + 256, bP + kt * HW + 64);
            CP_COMMIT();
        }

        // B fragments: 4 LDS.32 each, conflict-free
        float4 BB[4];
#pragma unroll
        for (int nt = 0; nt < 4; nt++) {
            const int n = wn + nt * 8 + g;
            BB[nt].x = Bsf[(t     ) * SB + n];
            BB[nt].y = Bsf[(t + 4 ) * SB + n];
            BB[nt].z = Bsf[(t + 8 ) * SB + n];
            BB[nt].w = Bsf[(t + 12) * SB + n];
        }

#pragma unroll
        for (int half = 0; half < 2; half++) {
            float4 AL[2], AH[2];
#pragma unroll
            for (int m = 0; m < 2; m++) {
                const int mr = wm + (half * 2 + m) * 16 + g;
                AL[m] = *(const float4*)&Asf[mr * SA + 4 * t];
                AH[m] = *(const float4*)&Asf[(mr + 8) * SA + 4 * t];
            }
            // k8 step 0 across all 8 accs of this half (independent MMAs)
#pragma unroll
            for (int m = 0; m < 2; m++) {
                const int mt = half * 2 + m;
#pragma unroll
                for (int nt = 0; nt < 4; nt++)
                    mma_tf32(acc[mt][nt], AL[m].x, AH[m].x, AL[m].y, AH[m].y,
                             BB[nt].x, BB[nt].y);
            }
            // k8 step 1 (same-acc reuse now 8 MMAs apart)
#pragma unroll
            for (int m = 0; m < 2; m++) {
                const int mt = half * 2 + m;
#pragma unroll
                for (int nt = 0; nt < 4; nt++)
                    mma_tf32(acc[mt][nt], AL[m].z, AH[m].z, AL[m].w, AH[m].w,
                             BB[nt].z, BB[nt].w);
            }
        }
    }

    __syncthreads();

    // epilogue: D fragments -> gmem
#pragma unroll
    for (int mt = 0; mt < 4; mt++) {
#pragma unroll
        for (int nt = 0; nt < 4; nt++) {
            const int row = m0 + wm + mt * 16 + g;
            const int col = n0 + wn + nt * 8 + 2 * t;
            float4 d = acc[mt][nt];
            *(float2*)(Cp + (size_t)row * HW + col)       = make_float2(d.x, d.y);
            *(float2*)(Cp + (size_t)(row + 8) * HW + col) = make_float2(d.z, d.w);
        }
    }
}

// ---------------------------------------------------------------------------
extern "C" void kernel_launch(void* const* d_in, const int* in_sizes, int n_in,
                              void* d_out, int out_size)
{
    const float* x     = (const float*)d_in[0];   // (4,256,64,64)
    const float* w_def = (const float*)d_in[1];   // (256,256,3,3)
    const float* w_off = (const float*)d_in[2];   // (18,256,3,3)
    float* out = (float*)d_out;                   // (4,256,64,64)

    cudaFuncSetAttribute(mma_gemm_kernel,
                         cudaFuncAttributeMaxDynamicSharedMemorySize, SMEM_GEMM_BYTES);

    round_a_kernel<<<(COUT * PDIM + 255) / 256, 256>>>(w_def);
    offsets_part_kernel<<<dim3(BATCH * 32, NSPLIT), 128>>>(x, w_off);
    gather_kernel<<<(BATCH * KK * HW + 255) / 256, 256>>>(x);
    mma_gemm_kernel<<<dim3(HW / BN, COUT / BM, BATCH), 256, SMEM_GEMM_BYTES>>>(out);
}